// round 2
// baseline (speedup 1.0000x reference)
#include <cuda_runtime.h>
#include <cuda_bf16.h>

// firing_model: next = -prev + tanh(prev @ x) from prev = 0 -> identically zero
// trajectory (tanh(0)=0 exactly in fp32). Output [499800, 69] is all zeros.
// Pure 138 MB zero-fill, HBM-store bound.
//
// R2: R1 was issue-bound (one STG.128 per thread, 33k tiny blocks -> occ 24%,
// DRAM 47%). Switch to a grid-stride loop with 4x unrolled STG.128 per
// iteration so each warp streams stores back-to-back at the LSU rate.

#ifndef FILL_BLOCKS
#define FILL_BLOCKS (148 * 8)
#endif
#define FILL_THREADS 256
#define FILL_UNROLL 4

__global__ void __launch_bounds__(FILL_THREADS)
firing_model_zero_fill_gs(float4* __restrict__ out, long long n4) {
    const long long stride = (long long)gridDim.x * FILL_THREADS;
    long long i = (long long)blockIdx.x * FILL_THREADS + threadIdx.x;
    const float4 z = make_float4(0.0f, 0.0f, 0.0f, 0.0f);

    // Main unrolled loop: 4 independent fully-coalesced STG.128 per iteration.
    for (; i + (FILL_UNROLL - 1) * stride < n4; i += FILL_UNROLL * stride) {
#pragma unroll
        for (int j = 0; j < FILL_UNROLL; j++) {
            out[i + (long long)j * stride] = z;
        }
    }
    // Remainder
    for (; i < n4; i += stride) {
        out[i] = z;
    }
}

__global__ void firing_model_zero_fill_tail(float* __restrict__ out,
                                            long long start, long long n) {
    long long i = start + (long long)blockIdx.x * blockDim.x + threadIdx.x;
    if (i < n) {
        out[i] = 0.0f;
    }
}

extern "C" void kernel_launch(void* const* d_in, const int* in_sizes, int n_in,
                              void* d_out, int out_size) {
    (void)d_in; (void)in_sizes; (void)n_in;

    float* out = (float*)d_out;
    long long n  = (long long)out_size;   // 34,486,200 floats expected
    long long n4 = n >> 2;                // exactly divisible for this shape
    long long tail_start = n4 << 2;

    if (n4 > 0) {
        firing_model_zero_fill_gs<<<FILL_BLOCKS, FILL_THREADS>>>((float4*)out, n4);
    }
    if (tail_start < n) {
        long long tail = n - tail_start;
        int blocks = (int)((tail + 255) / 256);
        firing_model_zero_fill_tail<<<blocks, 256>>>(out, tail_start, n);
    }
}

// round 3
// speedup vs baseline: 1.1846x; 1.1846x over previous
#include <cuda_runtime.h>
#include <cuda_bf16.h>

// firing_model: next = -prev + tanh(prev @ x) from prev = 0 -> identically
// zero trajectory (tanh(0) = 0 exactly in fp32). Output [499800, 69] is all
// zeros -> pure 138 MB zero-fill of d_out. HBM-write bound.
//
// R3: R1 (exact cover, 1 STG.128/thread) hit ~6.7 TB/s; grid-stride (R2)
// regressed. Keep exact-cover, but 2 contiguous STG.128 per thread with a
// streaming (.cs, evict-first) hint: half the blocks, block prologue
// amortized over 2 stores, no L2 pollution from dead write-allocated lines.

#define FILL_THREADS 256
#define F4_PER_THREAD 2   // each block covers FILL_THREADS * 2 float4s

__global__ void __launch_bounds__(FILL_THREADS)
firing_model_zero_fill2(float4* __restrict__ out, long long n4) {
    long long base = (long long)blockIdx.x * (FILL_THREADS * F4_PER_THREAD)
                   + threadIdx.x;
    const float4 z = make_float4(0.0f, 0.0f, 0.0f, 0.0f);

    long long i0 = base;
    long long i1 = base + FILL_THREADS;
    if (i0 < n4) __stcs(&out[i0], z);
    if (i1 < n4) __stcs(&out[i1], z);
}

__global__ void firing_model_zero_fill_tail(float* __restrict__ out,
                                            long long start, long long n) {
    long long i = start + (long long)blockIdx.x * blockDim.x + threadIdx.x;
    if (i < n) {
        out[i] = 0.0f;
    }
}

extern "C" void kernel_launch(void* const* d_in, const int* in_sizes, int n_in,
                              void* d_out, int out_size) {
    (void)d_in; (void)in_sizes; (void)n_in;

    float* out = (float*)d_out;
    long long n  = (long long)out_size;   // 34,486,200 floats expected
    long long n4 = n >> 2;                // 8,621,550 float4s (exact for this shape)
    long long tail_start = n4 << 2;

    if (n4 > 0) {
        long long per_block = FILL_THREADS * F4_PER_THREAD;
        long long blocks = (n4 + per_block - 1) / per_block;   // ~16,839
        firing_model_zero_fill2<<<(unsigned int)blocks, FILL_THREADS>>>(
            (float4*)out, n4);
    }
    if (tail_start < n) {  // not taken for this shape; defensive
        long long tail = n - tail_start;
        int blocks = (int)((tail + 255) / 256);
        firing_model_zero_fill_tail<<<blocks, 256>>>(out, tail_start, n);
    }
}